// round 13
// baseline (speedup 1.0000x reference)
#include <cuda_runtime.h>
#include <cuda_fp16.h>
#include <cstdint>

// ============================================================================
// MambaBlock, single-product fp16 HMMA (A and B fp16-rounded, fp32 acc).
// R13: 4-stage cp.async ring (3-chunk lookahead) to hide chunk load latency.
// ============================================================================

#define MROWS 16384
#define DDIM  1024
#define LSEQ  4096

#define BM 128
#define BN 128
#define BK 32
#define SP 40                    // SMEM row stride in fp16 (32 + 8 pad)
#define NTH 256

#define A_OF 0
#define B_OF (BM * SP * 2)       // 10240
#define STAGE_BYTES (2 * BM * SP * 2)   // 20480
#define NSTAGE 4
#define SMEMSZ (NSTAGE * STAGE_BYTES)   // 81920

__device__ float g_uv[(size_t)MROWS * 2 * DDIM];
__device__ __half g_xh[(size_t)MROWS * DDIM];
__device__ __half g_yh[(size_t)MROWS * DDIM];
__device__ __half g_wi[(size_t)2 * DDIM * DDIM];
__device__ __half g_wo[(size_t)DDIM * DDIM];

__device__ __forceinline__ void mma_f16(float* c, const uint32_t* a,
                                        uint32_t b0, uint32_t b1) {
    asm volatile(
        "mma.sync.aligned.m16n8k16.row.col.f32.f16.f16.f32 "
        "{%0,%1,%2,%3}, {%4,%5,%6,%7}, {%8,%9}, {%0,%1,%2,%3};"
        : "+f"(c[0]), "+f"(c[1]), "+f"(c[2]), "+f"(c[3])
        : "r"(a[0]), "r"(a[1]), "r"(a[2]), "r"(a[3]), "r"(b0), "r"(b1));
}

#define LDSM4(r0, r1, r2, r3, addr)                                        \
    asm volatile("ldmatrix.sync.aligned.m8n8.x4.shared.b16 {%0,%1,%2,%3}, [%4];" \
                 : "=r"(r0), "=r"(r1), "=r"(r2), "=r"(r3) : "r"(addr))

#define CPA16(dst, src) \
    asm volatile("cp.async.cg.shared.global [%0], [%1], 16;" :: "r"(dst), "l"(src))
#define CP_COMMIT() asm volatile("cp.async.commit_group;" ::: "memory")
#define CP_WAIT2()  asm volatile("cp.async.wait_group 2;" ::: "memory")
#define CP_WAIT0()  asm volatile("cp.async.wait_group 0;" ::: "memory")

// round fp32x4 -> 2 fp16x2 words
__global__ __launch_bounds__(256)
void cvt_round_kernel(const float* __restrict__ src, __half* __restrict__ dst) {
    size_t i4 = ((size_t)blockIdx.x * 256 + threadIdx.x) * 4;
    float4 v = *(const float4*)(src + i4);
    __half2 H0 = __floats2half2_rn(v.x, v.y);
    __half2 H1 = __floats2half2_rn(v.z, v.w);
    *(uint2*)((char*)dst + i4 * 2) =
        make_uint2(*reinterpret_cast<uint32_t*>(&H0), *reinterpret_cast<uint32_t*>(&H1));
}

// round Wi (2*D*D) and Wo (D*D) in a single launch
__global__ __launch_bounds__(256)
void cvt_round_w_kernel(const float* __restrict__ Wi, __half* __restrict__ wi,
                        const float* __restrict__ Wo, __half* __restrict__ wo) {
    size_t i4 = ((size_t)blockIdx.x * 256 + threadIdx.x) * 4;
    const size_t wiN = (size_t)2 * DDIM * DDIM;
    const float* src;
    char* dst;
    size_t off;
    if (i4 < wiN) { src = Wi; dst = (char*)wi; off = i4; }
    else          { src = Wo; dst = (char*)wo; off = i4 - wiN; }
    float4 v = *(const float4*)(src + off);
    __half2 H0 = __floats2half2_rn(v.x, v.y);
    __half2 H1 = __floats2half2_rn(v.z, v.w);
    *(uint2*)(dst + off * 2) =
        make_uint2(*reinterpret_cast<uint32_t*>(&H0), *reinterpret_cast<uint32_t*>(&H1));
}

// ---------------------------------------------------------------------------
// C[M,N] = A[M,K] @ B[N,K]^T + bias   (fp16 operands, fp32 accumulate)
// ---------------------------------------------------------------------------
template <int N, int K>
__global__ __launch_bounds__(NTH, 2)
void gemm_mma(const __half* __restrict__ A, const __half* __restrict__ B,
              const float* __restrict__ bias, float* __restrict__ C) {
    extern __shared__ __align__(16) char sm[];
    const uint32_t smb = (uint32_t)__cvta_generic_to_shared(sm);
    const int tid  = threadIdx.x;
    const int lane = tid & 31;
    const int wid  = tid >> 5;
    const int wm   = wid & 3;
    const int wn   = wid >> 2;
    const int qr   = lane >> 2;
    const int qc   = (lane & 3) * 2;
    const int row0 = blockIdx.y * BM;
    const int col0 = blockIdx.x * BN;

    const int m8 = lane >> 3;
    const int rr = lane & 7;
    const uint32_t aLane = (uint32_t)(((wm * 32 + (m8 & 1) * 8 + rr) * SP + (m8 >> 1) * 8) * 2);
    const uint32_t bLane = (uint32_t)(((wn * 64 + (m8 >> 1) * 8 + rr) * SP + (m8 & 1) * 8) * 2);

    const int l_r0 = tid >> 2;       // rows 0..63, +64
    const int l_c  = (tid & 3) * 16;

    float acc[2][8][4];
#pragma unroll
    for (int i = 0; i < 2; i++)
#pragma unroll
        for (int j = 0; j < 8; j++)
#pragma unroll
            for (int k = 0; k < 4; k++) acc[i][j][k] = 0.f;

    const char* pA = (const char*)(A + (size_t)row0 * K);
    const char* pB = (const char*)(B + (size_t)col0 * K);

#define LOAD_STAGE(stageOff, kt) do {                                          \
    const uint32_t so_ = smb + (stageOff);                                     \
    const size_t kb_ = (size_t)(kt) * 2;                                       \
    _Pragma("unroll")                                                          \
    for (int rep = 0; rep < 2; rep++) {                                        \
        int r = l_r0 + rep * 64;                                               \
        uint32_t d = so_ + (uint32_t)(r * (SP * 2) + l_c);                     \
        size_t g = (size_t)r * (K * 2) + kb_ + l_c;                            \
        CPA16(d + A_OF, pA + g);                                               \
        CPA16(d + B_OF, pB + g);                                               \
    }                                                                          \
} while (0)

    // prologue: stages 0,1,2
    LOAD_STAGE(0, 0);
    CP_COMMIT();
    LOAD_STAGE(STAGE_BYTES, BK);
    CP_COMMIT();
    LOAD_STAGE(2 * STAGE_BYTES, 2 * BK);
    CP_COMMIT();

    constexpr int NCH = K / BK;      // 16
    int s_cur = 0, s_nxt = 3;        // ck % 4, (ck+3) % 4
#pragma unroll 1
    for (int ck = 0; ck < NCH; ck++) {
        if (ck + 1 < NCH) CP_WAIT2(); else CP_WAIT0();
        __syncthreads();             // seals compute of ck-1 -> stage s_nxt reusable
        if (ck + 3 < NCH) {
            LOAD_STAGE((uint32_t)(s_nxt * STAGE_BYTES), (ck + 3) * BK);
            CP_COMMIT();
        }

        const uint32_t sto = smb + (uint32_t)(s_cur * STAGE_BYTES);
#pragma unroll
        for (int kb = 0; kb < BK; kb += 16) {
            uint32_t aa[2][4], bb[4][4];
#pragma unroll
            for (int mt = 0; mt < 2; mt++) {
                uint32_t ao = sto + aLane + (uint32_t)((mt * 16 * SP + kb) * 2);
                LDSM4(aa[mt][0], aa[mt][1], aa[mt][2], aa[mt][3], ao + A_OF);
            }
#pragma unroll
            for (int ntp = 0; ntp < 4; ntp++) {
                uint32_t bo = sto + bLane + (uint32_t)((ntp * 16 * SP + kb) * 2);
                LDSM4(bb[ntp][0], bb[ntp][1], bb[ntp][2], bb[ntp][3], bo + B_OF);
            }
#pragma unroll
            for (int mt = 0; mt < 2; mt++)
#pragma unroll
                for (int ntp = 0; ntp < 4; ntp++) {
                    mma_f16(acc[mt][2 * ntp],     aa[mt], bb[ntp][0], bb[ntp][1]);
                    mma_f16(acc[mt][2 * ntp + 1], aa[mt], bb[ntp][2], bb[ntp][3]);
                }
        }
        s_cur = (s_cur + 1) & 3;
        s_nxt = (s_nxt + 1) & 3;
    }
#undef LOAD_STAGE

    // epilogue: bias + store
#pragma unroll
    for (int mt = 0; mt < 2; mt++) {
        int row = row0 + wm * 32 + mt * 16 + qr;
#pragma unroll
        for (int nt = 0; nt < 8; nt++) {
            int col = col0 + wn * 64 + nt * 8 + qc;
            float b0 = __ldg(&bias[col]);
            float b1 = __ldg(&bias[col + 1]);
            float2 o0 = make_float2(acc[mt][nt][0] + b0, acc[mt][nt][1] + b1);
            float2 o1 = make_float2(acc[mt][nt][2] + b0, acc[mt][nt][3] + b1);
            *(float2*)(C + (size_t)row * N + col) = o0;
            *(float2*)(C + (size_t)(row + 8) * N + col) = o1;
        }
    }
}

// ---------------------------------------------------------------------------
// depthwise conv3 + silu gate; emits y as fp16
// ---------------------------------------------------------------------------
__global__ __launch_bounds__(256)
void conv_gate_kernel(const float* __restrict__ Wc, const float* __restrict__ bc) {
    int idx = blockIdx.x * blockDim.x + threadIdx.x;
    int m = idx >> 8;
    int d = (idx & 255) << 2;
    int l = m & (LSEQ - 1);

    const float* urow = g_uv + (size_t)m * (2 * DDIM);
    const float* vrow = urow + DDIM;

    float4 vc = *(const float4*)(vrow + d);
    float4 vp = make_float4(0.f, 0.f, 0.f, 0.f);
    float4 vn = make_float4(0.f, 0.f, 0.f, 0.f);
    if (l > 0)        vp = *(const float4*)(vrow - 2 * DDIM + d);
    if (l < LSEQ - 1) vn = *(const float4*)(vrow + 2 * DDIM + d);
    float4 uu = *(const float4*)(urow + d);

    float p[4] = {vp.x, vp.y, vp.z, vp.w};
    float c[4] = {vc.x, vc.y, vc.z, vc.w};
    float n[4] = {vn.x, vn.y, vn.z, vn.w};
    float u[4] = {uu.x, uu.y, uu.z, uu.w};
    float o[4];
#pragma unroll
    for (int j = 0; j < 4; j++) {
        int dd = d + j;
        float t = fmaf(p[j], Wc[dd * 3 + 0],
                  fmaf(c[j], Wc[dd * 3 + 1],
                  fmaf(n[j], Wc[dd * 3 + 2], bc[dd])));
        float s = 1.f / (1.f + __expf(-t));
        o[j] = t * s * u[j];
    }
    __half2 H0 = __floats2half2_rn(o[0], o[1]);
    __half2 H1 = __floats2half2_rn(o[2], o[3]);
    size_t off = ((size_t)m * DDIM + d) * 2;
    *(uint2*)((char*)g_yh + off) = make_uint2(*reinterpret_cast<uint32_t*>(&H0),
                                              *reinterpret_cast<uint32_t*>(&H1));
}

// ---------------------------------------------------------------------------
extern "C" void kernel_launch(void* const* d_in, const int* in_sizes, int n_in,
                              void* d_out, int out_size) {
    const float* x  = (const float*)d_in[0];
    const float* Wi = (const float*)d_in[1];
    const float* bi = (const float*)d_in[2];
    const float* Wc = (const float*)d_in[3];
    const float* bc = (const float*)d_in[4];
    const float* Wo = (const float*)d_in[5];
    const float* bo = (const float*)d_in[6];
    float* out = (float*)d_out;

    float* uv_ptr;
    __half *xh, *yh, *wi, *wo;
    cudaGetSymbolAddress((void**)&uv_ptr, g_uv);
    cudaGetSymbolAddress((void**)&xh, g_xh);
    cudaGetSymbolAddress((void**)&yh, g_yh);
    cudaGetSymbolAddress((void**)&wi, g_wi);
    cudaGetSymbolAddress((void**)&wo, g_wo);

    cudaFuncSetAttribute(gemm_mma<2 * DDIM, DDIM>,
                         cudaFuncAttributeMaxDynamicSharedMemorySize, SMEMSZ);
    cudaFuncSetAttribute(gemm_mma<DDIM, DDIM>,
                         cudaFuncAttributeMaxDynamicSharedMemorySize, SMEMSZ);

    // round x to fp16; Wi+Wo in one launch
    cvt_round_kernel<<<(MROWS * DDIM) / 1024, 256>>>(x, xh);
    cvt_round_w_kernel<<<(3 * DDIM * DDIM) / 1024, 256>>>(Wi, wi, Wo, wo);

    {   // GEMM1: uv = x @ Wi^T + bi
        dim3 grid(2 * DDIM / BN, MROWS / BM);
        gemm_mma<2 * DDIM, DDIM><<<grid, NTH, SMEMSZ>>>(xh, wi, bi, uv_ptr);
    }
    {   // conv + silu gate -> y fp16
        int total = MROWS * (DDIM / 4);
        conv_gate_kernel<<<total / 256, 256>>>(Wc, bc);
    }
    {   // GEMM2: out = y @ Wo^T + bo
        dim3 grid(DDIM / BN, MROWS / BM);
        gemm_mma<DDIM, DDIM><<<grid, NTH, SMEMSZ>>>(yh, wo, bo, out);
    }
}

// round 17
// speedup vs baseline: 1.1573x; 1.1573x over previous
#include <cuda_runtime.h>
#include <cuda_fp16.h>
#include <cstdint>

// ============================================================================
// MambaBlock, single-product fp16 HMMA, fp32 accumulate.
// R14: BK=64 (half the chunk/barrier count), uv scratch in fp16.
// ============================================================================

#define MROWS 16384
#define DDIM  1024
#define LSEQ  4096

#define BM 128
#define BN 128
#define BK 64
#define SP 72                    // SMEM row stride in fp16 (64 + 8 pad)
#define NTH 256

#define A_OF 0
#define B_OF (BM * SP * 2)       // 18432
#define STAGE_BYTES (2 * BM * SP * 2)   // 36864
#define NSTAGE 3
#define SMEMSZ (NSTAGE * STAGE_BYTES)   // 110592

__device__ __half g_uvh[(size_t)MROWS * 2 * DDIM];   // [M,2048] fp16: u | v
__device__ __half g_xh[(size_t)MROWS * DDIM];
__device__ __half g_yh[(size_t)MROWS * DDIM];
__device__ __half g_wi[(size_t)2 * DDIM * DDIM];
__device__ __half g_wo[(size_t)DDIM * DDIM];

__device__ __forceinline__ void mma_f16(float* c, const uint32_t* a,
                                        uint32_t b0, uint32_t b1) {
    asm volatile(
        "mma.sync.aligned.m16n8k16.row.col.f32.f16.f16.f32 "
        "{%0,%1,%2,%3}, {%4,%5,%6,%7}, {%8,%9}, {%0,%1,%2,%3};"
        : "+f"(c[0]), "+f"(c[1]), "+f"(c[2]), "+f"(c[3])
        : "r"(a[0]), "r"(a[1]), "r"(a[2]), "r"(a[3]), "r"(b0), "r"(b1));
}

#define LDSM4(r0, r1, r2, r3, addr)                                        \
    asm volatile("ldmatrix.sync.aligned.m8n8.x4.shared.b16 {%0,%1,%2,%3}, [%4];" \
                 : "=r"(r0), "=r"(r1), "=r"(r2), "=r"(r3) : "r"(addr))

#define CPA16(dst, src) \
    asm volatile("cp.async.cg.shared.global [%0], [%1], 16;" :: "r"(dst), "l"(src))
#define CP_COMMIT() asm volatile("cp.async.commit_group;" ::: "memory")
#define CP_WAIT1()  asm volatile("cp.async.wait_group 1;" ::: "memory")
#define CP_WAIT0()  asm volatile("cp.async.wait_group 0;" ::: "memory")

// round fp32x4 -> 2 fp16x2 words
__global__ __launch_bounds__(256)
void cvt_round_kernel(const float* __restrict__ src, __half* __restrict__ dst) {
    size_t i4 = ((size_t)blockIdx.x * 256 + threadIdx.x) * 4;
    float4 v = *(const float4*)(src + i4);
    __half2 H0 = __floats2half2_rn(v.x, v.y);
    __half2 H1 = __floats2half2_rn(v.z, v.w);
    *(uint2*)((char*)dst + i4 * 2) =
        make_uint2(*reinterpret_cast<uint32_t*>(&H0), *reinterpret_cast<uint32_t*>(&H1));
}

// round Wi (2*D*D) and Wo (D*D) in a single launch
__global__ __launch_bounds__(256)
void cvt_round_w_kernel(const float* __restrict__ Wi, __half* __restrict__ wi,
                        const float* __restrict__ Wo, __half* __restrict__ wo) {
    size_t i4 = ((size_t)blockIdx.x * 256 + threadIdx.x) * 4;
    const size_t wiN = (size_t)2 * DDIM * DDIM;
    const float* src;
    char* dst;
    size_t off;
    if (i4 < wiN) { src = Wi; dst = (char*)wi; off = i4; }
    else          { src = Wo; dst = (char*)wo; off = i4 - wiN; }
    float4 v = *(const float4*)(src + off);
    __half2 H0 = __floats2half2_rn(v.x, v.y);
    __half2 H1 = __floats2half2_rn(v.z, v.w);
    *(uint2*)(dst + off * 2) =
        make_uint2(*reinterpret_cast<uint32_t*>(&H0), *reinterpret_cast<uint32_t*>(&H1));
}

// ---------------------------------------------------------------------------
// C[M,N] = A[M,K] @ B[N,K]^T + bias.  HALF_OUT: C is fp16, else fp32.
// ---------------------------------------------------------------------------
template <int N, int K, bool HALF_OUT>
__global__ __launch_bounds__(NTH, 2)
void gemm_mma(const __half* __restrict__ A, const __half* __restrict__ B,
              const float* __restrict__ bias, void* __restrict__ Cv) {
    extern __shared__ __align__(16) char sm[];
    const uint32_t smb = (uint32_t)__cvta_generic_to_shared(sm);
    const int tid  = threadIdx.x;
    const int lane = tid & 31;
    const int wid  = tid >> 5;
    const int wm   = wid & 3;
    const int wn   = wid >> 2;
    const int qr   = lane >> 2;
    const int qc   = (lane & 3) * 2;
    const int row0 = blockIdx.y * BM;
    const int col0 = blockIdx.x * BN;

    const int m8 = lane >> 3;
    const int rr = lane & 7;
    const uint32_t aLane = (uint32_t)(((wm * 32 + (m8 & 1) * 8 + rr) * SP + (m8 >> 1) * 8) * 2);
    const uint32_t bLane = (uint32_t)(((wn * 64 + (m8 >> 1) * 8 + rr) * SP + (m8 & 1) * 8) * 2);

    const int l_r0 = tid >> 3;       // rows 0..31, +32 per rep (4 reps)
    const int l_c  = (tid & 7) * 16; // byte col within 128B row

    float acc[2][8][4];
#pragma unroll
    for (int i = 0; i < 2; i++)
#pragma unroll
        for (int j = 0; j < 8; j++)
#pragma unroll
            for (int k = 0; k < 4; k++) acc[i][j][k] = 0.f;

    const char* pA = (const char*)(A + (size_t)row0 * K);
    const char* pB = (const char*)(B + (size_t)col0 * K);

#define LOAD_STAGE(stageOff, kt) do {                                          \
    const uint32_t so_ = smb + (stageOff);                                     \
    const size_t kb_ = (size_t)(kt) * 2;                                       \
    _Pragma("unroll")                                                          \
    for (int rep = 0; rep < 4; rep++) {                                        \
        int r = l_r0 + rep * 32;                                               \
        uint32_t d = so_ + (uint32_t)(r * (SP * 2) + l_c);                     \
        size_t g = (size_t)r * (K * 2) + kb_ + l_c;                            \
        CPA16(d + A_OF, pA + g);                                               \
        CPA16(d + B_OF, pB + g);                                               \
    }                                                                          \
} while (0)

    // prologue: stages 0, 1
    LOAD_STAGE(0, 0);
    CP_COMMIT();
    LOAD_STAGE(STAGE_BYTES, BK);
    CP_COMMIT();

    constexpr int NCH = K / BK;      // 16
    int s_cur = 0, s_nxt = 2;
#pragma unroll 1
    for (int ck = 0; ck < NCH; ck++) {
        if (ck + 1 < NCH) CP_WAIT1(); else CP_WAIT0();
        __syncthreads();
        if (ck + 2 < NCH) {
            LOAD_STAGE((uint32_t)(s_nxt * STAGE_BYTES), (ck + 2) * BK);
            CP_COMMIT();
        }

        const uint32_t sto = smb + (uint32_t)(s_cur * STAGE_BYTES);
#pragma unroll
        for (int kb = 0; kb < BK; kb += 16) {
            uint32_t aa[2][4], bb[4][4];
#pragma unroll
            for (int mt = 0; mt < 2; mt++) {
                uint32_t ao = sto + aLane + (uint32_t)((mt * 16 * SP + kb) * 2);
                LDSM4(aa[mt][0], aa[mt][1], aa[mt][2], aa[mt][3], ao + A_OF);
            }
#pragma unroll
            for (int ntp = 0; ntp < 4; ntp++) {
                uint32_t bo = sto + bLane + (uint32_t)((ntp * 16 * SP + kb) * 2);
                LDSM4(bb[ntp][0], bb[ntp][1], bb[ntp][2], bb[ntp][3], bo + B_OF);
            }
#pragma unroll
            for (int mt = 0; mt < 2; mt++)
#pragma unroll
                for (int ntp = 0; ntp < 4; ntp++) {
                    mma_f16(acc[mt][2 * ntp],     aa[mt], bb[ntp][0], bb[ntp][1]);
                    mma_f16(acc[mt][2 * ntp + 1], aa[mt], bb[ntp][2], bb[ntp][3]);
                }
        }
        s_cur = (s_cur == 2) ? 0 : s_cur + 1;
        s_nxt = (s_nxt == 2) ? 0 : s_nxt + 1;
    }
#undef LOAD_STAGE

    // epilogue: bias + store
#pragma unroll
    for (int mt = 0; mt < 2; mt++) {
        int row = row0 + wm * 32 + mt * 16 + qr;
#pragma unroll
        for (int nt = 0; nt < 8; nt++) {
            int col = col0 + wn * 64 + nt * 8 + qc;
            float b0 = __ldg(&bias[col]);
            float b1 = __ldg(&bias[col + 1]);
            float v00 = acc[mt][nt][0] + b0, v01 = acc[mt][nt][1] + b1;
            float v10 = acc[mt][nt][2] + b0, v11 = acc[mt][nt][3] + b1;
            if (HALF_OUT) {
                __half* C = (__half*)Cv;
                __half2 h0 = __floats2half2_rn(v00, v01);
                __half2 h1 = __floats2half2_rn(v10, v11);
                *(uint32_t*)(C + (size_t)row * N + col)       = *reinterpret_cast<uint32_t*>(&h0);
                *(uint32_t*)(C + (size_t)(row + 8) * N + col) = *reinterpret_cast<uint32_t*>(&h1);
            } else {
                float* C = (float*)Cv;
                *(float2*)(C + (size_t)row * N + col)       = make_float2(v00, v01);
                *(float2*)(C + (size_t)(row + 8) * N + col) = make_float2(v10, v11);
            }
        }
    }
}

// ---------------------------------------------------------------------------
// depthwise conv3 + silu gate; uv fp16 in, y fp16 out (compute in fp32)
// ---------------------------------------------------------------------------
__device__ __forceinline__ void h4_to_f4(uint2 w, float* f) {
    __half2 a = *reinterpret_cast<__half2*>(&w.x);
    __half2 b = *reinterpret_cast<__half2*>(&w.y);
    f[0] = __low2float(a); f[1] = __high2float(a);
    f[2] = __low2float(b); f[3] = __high2float(b);
}

__global__ __launch_bounds__(256)
void conv_gate_kernel(const float* __restrict__ Wc, const float* __restrict__ bc) {
    int idx = blockIdx.x * blockDim.x + threadIdx.x;
    int m = idx >> 8;
    int d = (idx & 255) << 2;
    int l = m & (LSEQ - 1);

    const __half* urow = g_uvh + (size_t)m * (2 * DDIM);
    const __half* vrow = urow + DDIM;

    float c[4], p[4] = {0.f, 0.f, 0.f, 0.f}, n[4] = {0.f, 0.f, 0.f, 0.f}, u[4];
    h4_to_f4(*(const uint2*)(vrow + d), c);
    if (l > 0)        h4_to_f4(*(const uint2*)(vrow - 2 * DDIM + d), p);
    if (l < LSEQ - 1) h4_to_f4(*(const uint2*)(vrow + 2 * DDIM + d), n);
    h4_to_f4(*(const uint2*)(urow + d), u);

    float o[4];
#pragma unroll
    for (int j = 0; j < 4; j++) {
        int dd = d + j;
        float t = fmaf(p[j], Wc[dd * 3 + 0],
                  fmaf(c[j], Wc[dd * 3 + 1],
                  fmaf(n[j], Wc[dd * 3 + 2], bc[dd])));
        float s = 1.f / (1.f + __expf(-t));
        o[j] = t * s * u[j];
    }
    __half2 H0 = __floats2half2_rn(o[0], o[1]);
    __half2 H1 = __floats2half2_rn(o[2], o[3]);
    size_t off = ((size_t)m * DDIM + d) * 2;
    *(uint2*)((char*)g_yh + off) = make_uint2(*reinterpret_cast<uint32_t*>(&H0),
                                              *reinterpret_cast<uint32_t*>(&H1));
}

// ---------------------------------------------------------------------------
extern "C" void kernel_launch(void* const* d_in, const int* in_sizes, int n_in,
                              void* d_out, int out_size) {
    const float* x  = (const float*)d_in[0];
    const float* Wi = (const float*)d_in[1];
    const float* bi = (const float*)d_in[2];
    const float* Wc = (const float*)d_in[3];
    const float* bc = (const float*)d_in[4];
    const float* Wo = (const float*)d_in[5];
    const float* bo = (const float*)d_in[6];
    float* out = (float*)d_out;

    __half *uvh, *xh, *yh, *wi, *wo;
    cudaGetSymbolAddress((void**)&uvh, g_uvh);
    cudaGetSymbolAddress((void**)&xh, g_xh);
    cudaGetSymbolAddress((void**)&yh, g_yh);
    cudaGetSymbolAddress((void**)&wi, g_wi);
    cudaGetSymbolAddress((void**)&wo, g_wo);

    cudaFuncSetAttribute(gemm_mma<2 * DDIM, DDIM, true>,
                         cudaFuncAttributeMaxDynamicSharedMemorySize, SMEMSZ);
    cudaFuncSetAttribute(gemm_mma<DDIM, DDIM, false>,
                         cudaFuncAttributeMaxDynamicSharedMemorySize, SMEMSZ);

    // round x to fp16; Wi+Wo in one launch
    cvt_round_kernel<<<(MROWS * DDIM) / 1024, 256>>>(x, xh);
    cvt_round_w_kernel<<<(3 * DDIM * DDIM) / 1024, 256>>>(Wi, wi, Wo, wo);

    {   // GEMM1: uv(fp16) = x @ Wi^T + bi
        dim3 grid(2 * DDIM / BN, MROWS / BM);
        gemm_mma<2 * DDIM, DDIM, true><<<grid, NTH, SMEMSZ>>>(xh, wi, bi, uvh);
    }
    {   // conv + silu gate -> y fp16
        int total = MROWS * (DDIM / 4);
        conv_gate_kernel<<<total / 256, 256>>>(Wc, bc);
    }
    {   // GEMM2: out(fp32) = y @ Wo^T + bo
        dim3 grid(DDIM / BN, MROWS / BM);
        gemm_mma<DDIM, DDIM, false><<<grid, NTH, SMEMSZ>>>(yh, wo, bo, out);
    }
}